// round 1
// baseline (speedup 1.0000x reference)
#include <cuda_runtime.h>
#include <cuda_bf16.h>

// Problem constants (fixed by the reference)
#define NTOK   8192
#define DMODEL 1024
#define DHID   4096
#define NEXP   8
#define CAP    2048

// ---------------- scratch (allocation-free: __device__ globals) ------------
__device__ int   g_route[NTOK];
__device__ int   g_toklist[NEXP * CAP];
__device__ int   g_count[NEXP];
__device__ float g_h[(size_t)NEXP * CAP * DHID];   // 268 MB intermediate activations

// ---------------- router: logits + argmax (top_k = 1) ---------------------
// One warp per token, 8 tokens per block, Wg cached transposed in SMEM.
__global__ __launch_bounds__(256) void moe_router(const float* __restrict__ x,
                                                  const float* __restrict__ Wg,
                                                  const float* __restrict__ bg) {
    __shared__ float sWgT[NEXP][DMODEL];   // 32 KB, [e][d] for conflict-free reads
    int tid = threadIdx.x;
    for (int i = tid; i < DMODEL * NEXP; i += 256) {
        int d = i >> 3, e = i & 7;
        sWgT[e][d] = Wg[i];                // Wg is [d][e] row-major
    }
    __syncthreads();

    int wid = tid >> 5, lane = tid & 31;
    int token = blockIdx.x * 8 + wid;
    const float* xr = x + (size_t)token * DMODEL;

    float acc[NEXP];
#pragma unroll
    for (int e = 0; e < NEXP; e++) acc[e] = 0.f;

    for (int d = lane; d < DMODEL; d += 32) {
        float xv = xr[d];
#pragma unroll
        for (int e = 0; e < NEXP; e++) acc[e] += xv * sWgT[e][d];
    }
#pragma unroll
    for (int e = 0; e < NEXP; e++) {
#pragma unroll
        for (int off = 16; off > 0; off >>= 1)
            acc[e] += __shfl_xor_sync(0xffffffffu, acc[e], off);
    }
    if (lane == 0) {
        int best = 0;
        float bv = acc[0] + bg[0];
#pragma unroll
        for (int e = 1; e < NEXP; e++) {
            float v = acc[e] + bg[e];
            if (v > bv) { bv = v; best = e; }   // strict > : first-max tie-break (matches top_k)
        }
        g_route[token] = best;
    }
}

// ---------------- ordered capacity scan ------------------------------------
// Single block, 8 warps; warp e walks all tokens IN ORDER and assigns
// positions via ballot-prefix — exactly reproducing jnp.cumsum ordering.
__global__ __launch_bounds__(256) void moe_scan() {
    int tid = threadIdx.x;
    for (int i = tid; i < NEXP * CAP; i += 256) g_toklist[i] = -1;
    __syncthreads();

    int wid = tid >> 5, lane = tid & 31;   // wid == expert id (8 warps)
    int base = 0;
    for (int c = 0; c < NTOK / 32; c++) {
        int token = c * 32 + lane;
        int r = g_route[token];
        unsigned mask = __ballot_sync(0xffffffffu, r == wid);
        if (r == wid) {
            int pos = base + __popc(mask & ((1u << lane) - 1u));
            if (pos < CAP) g_toklist[wid * CAP + pos] = token;
        }
        base += __popc(mask);
    }
    if (lane == 0) g_count[wid] = base < CAP ? base : CAP;
}

// ---------------- tiled fp32 GEMMs -----------------------------------------
// 128x128 tile, BK=8, 256 threads, 8x8 per thread.
#define BM 128
#define BN 128
#define BK 8

// GEMM1: h[e, row, :] = relu( x[tok[row]] @ W1[e] + b1[e] )   K=1024, N=4096
__global__ __launch_bounds__(256) void moe_ffn1(const float* __restrict__ x,
                                                const float* __restrict__ W1,
                                                const float* __restrict__ b1) {
    int e = blockIdx.z;
    int count = g_count[e];
    int rowBase = blockIdx.y * BM;
    if (rowBase >= count) return;
    int colBase = blockIdx.x * BN;

    __shared__ float As[BK][BM];
    __shared__ float Bs[BK][BN];
    __shared__ int   sTok[BM];

    int tid = threadIdx.x;
    for (int i = tid; i < BM; i += 256) {
        int row = rowBase + i;
        sTok[i] = (row < count) ? g_toklist[e * CAP + row] : -1;
    }
    __syncthreads();

    const float* B    = W1 + (size_t)e * DMODEL * DHID + colBase;
    const float* bias = b1 + (size_t)e * DHID + colBase;

    int aRow = tid >> 1;
    int aK   = (tid & 1) * 4;
    int bRow = tid >> 5;
    int bCol = (tid & 31) * 4;
    int tx = tid & 15, ty = tid >> 4;

    int tokA = sTok[aRow];
    const float* aPtr = x + (size_t)(tokA >= 0 ? tokA : 0) * DMODEL + aK;

    float acc[8][8];
#pragma unroll
    for (int i = 0; i < 8; i++)
#pragma unroll
        for (int j = 0; j < 8; j++) acc[i][j] = 0.f;

    for (int k0 = 0; k0 < DMODEL; k0 += BK) {
        float4 av = make_float4(0.f, 0.f, 0.f, 0.f);
        if (tokA >= 0) av = *(const float4*)(aPtr + k0);
        As[aK + 0][aRow] = av.x;
        As[aK + 1][aRow] = av.y;
        As[aK + 2][aRow] = av.z;
        As[aK + 3][aRow] = av.w;
        *(float4*)&Bs[bRow][bCol] =
            *(const float4*)(B + (size_t)(k0 + bRow) * DHID + bCol);
        __syncthreads();
#pragma unroll
        for (int k = 0; k < BK; k++) {
            float a[8], b[8];
#pragma unroll
            for (int i = 0; i < 8; i++) a[i] = As[k][ty * 8 + i];
#pragma unroll
            for (int j = 0; j < 8; j++) b[j] = Bs[k][tx * 8 + j];
#pragma unroll
            for (int i = 0; i < 8; i++)
#pragma unroll
                for (int j = 0; j < 8; j++) acc[i][j] += a[i] * b[j];
        }
        __syncthreads();
    }

#pragma unroll
    for (int i = 0; i < 8; i++) {
        int row = ty * 8 + i;
        if (sTok[row] < 0) continue;
        float* outp = g_h + ((size_t)e * CAP + rowBase + row) * DHID + colBase + tx * 8;
#pragma unroll
        for (int j4 = 0; j4 < 2; j4++) {
            float4 v;
            float v0 = acc[i][j4 * 4 + 0] + bias[tx * 8 + j4 * 4 + 0];
            float v1 = acc[i][j4 * 4 + 1] + bias[tx * 8 + j4 * 4 + 1];
            float v2 = acc[i][j4 * 4 + 2] + bias[tx * 8 + j4 * 4 + 2];
            float v3 = acc[i][j4 * 4 + 3] + bias[tx * 8 + j4 * 4 + 3];
            v.x = v0 > 0.f ? v0 : 0.f;
            v.y = v1 > 0.f ? v1 : 0.f;
            v.z = v2 > 0.f ? v2 : 0.f;
            v.w = v3 > 0.f ? v3 : 0.f;
            *(float4*)(outp + j4 * 4) = v;
        }
    }
}

// GEMM2: out[tok[row]] = h[e,row,:] @ W2[e] + b2[e]   K=4096, N=1024
__global__ __launch_bounds__(256) void moe_ffn2(const float* __restrict__ W2,
                                                const float* __restrict__ b2,
                                                float* __restrict__ out) {
    int e = blockIdx.z;
    int count = g_count[e];
    int rowBase = blockIdx.y * BM;
    if (rowBase >= count) return;
    int colBase = blockIdx.x * BN;

    __shared__ float As[BK][BM];
    __shared__ float Bs[BK][BN];
    __shared__ int   sTok[BM];

    int tid = threadIdx.x;
    for (int i = tid; i < BM; i += 256) {
        int row = rowBase + i;
        sTok[i] = (row < count) ? g_toklist[e * CAP + row] : -1;
    }
    __syncthreads();

    const float* A    = g_h + ((size_t)e * CAP + rowBase) * DHID;
    const float* B    = W2 + (size_t)e * DHID * DMODEL + colBase;
    const float* bias = b2 + (size_t)e * DMODEL + colBase;

    int aRow = tid >> 1;
    int aK   = (tid & 1) * 4;
    int bRow = tid >> 5;
    int bCol = (tid & 31) * 4;
    int tx = tid & 15, ty = tid >> 4;

    bool aValid = (rowBase + aRow) < count;   // never read uninitialized g_h
    const float* aPtr = A + (size_t)aRow * DHID + aK;

    float acc[8][8];
#pragma unroll
    for (int i = 0; i < 8; i++)
#pragma unroll
        for (int j = 0; j < 8; j++) acc[i][j] = 0.f;

    for (int k0 = 0; k0 < DHID; k0 += BK) {
        float4 av = make_float4(0.f, 0.f, 0.f, 0.f);
        if (aValid) av = *(const float4*)(aPtr + k0);
        As[aK + 0][aRow] = av.x;
        As[aK + 1][aRow] = av.y;
        As[aK + 2][aRow] = av.z;
        As[aK + 3][aRow] = av.w;
        *(float4*)&Bs[bRow][bCol] =
            *(const float4*)(B + (size_t)(k0 + bRow) * DMODEL + bCol);
        __syncthreads();
#pragma unroll
        for (int k = 0; k < BK; k++) {
            float a[8], b[8];
#pragma unroll
            for (int i = 0; i < 8; i++) a[i] = As[k][ty * 8 + i];
#pragma unroll
            for (int j = 0; j < 8; j++) b[j] = Bs[k][tx * 8 + j];
#pragma unroll
            for (int i = 0; i < 8; i++)
#pragma unroll
                for (int j = 0; j < 8; j++) acc[i][j] += a[i] * b[j];
        }
        __syncthreads();
    }

#pragma unroll
    for (int i = 0; i < 8; i++) {
        int row = ty * 8 + i;
        int tok = sTok[row];
        if (tok < 0) continue;
        float* outp = out + (size_t)tok * DMODEL + colBase + tx * 8;
#pragma unroll
        for (int j4 = 0; j4 < 2; j4++) {
            float4 v;
            v.x = acc[i][j4 * 4 + 0] + bias[tx * 8 + j4 * 4 + 0];
            v.y = acc[i][j4 * 4 + 1] + bias[tx * 8 + j4 * 4 + 1];
            v.z = acc[i][j4 * 4 + 2] + bias[tx * 8 + j4 * 4 + 2];
            v.w = acc[i][j4 * 4 + 3] + bias[tx * 8 + j4 * 4 + 3];
            *(float4*)(outp + j4 * 4) = v;
        }
    }
}

// ---------------- launch ----------------------------------------------------
extern "C" void kernel_launch(void* const* d_in, const int* in_sizes, int n_in,
                              void* d_out, int out_size) {
    const float* x  = (const float*)d_in[0];
    const float* Wg = (const float*)d_in[1];
    const float* bg = (const float*)d_in[2];
    const float* W1 = (const float*)d_in[3];
    const float* b1 = (const float*)d_in[4];
    const float* W2 = (const float*)d_in[5];
    const float* b2 = (const float*)d_in[6];
    // d_in[7] = top_k (fixed to 1 by the reference)
    float* out = (float*)d_out;

    // dropped tokens must be exactly zero; d_out is poisoned
    cudaMemsetAsync(d_out, 0, (size_t)out_size * sizeof(float));

    moe_router<<<NTOK / 8, 256>>>(x, Wg, bg);
    moe_scan<<<1, 256>>>();
    moe_ffn1<<<dim3(DHID / BN, CAP / BM, NEXP), 256>>>(x, W1, b1);
    moe_ffn2<<<dim3(DMODEL / BN, CAP / BM, NEXP), 256>>>(W2, b2, out);
}

// round 2
// speedup vs baseline: 1.3925x; 1.3925x over previous
#include <cuda_runtime.h>
#include <cuda_bf16.h>
#include <cstdint>

// Problem constants (fixed by the reference)
#define NTOK   8192
#define DMODEL 1024
#define DHID   4096
#define NEXP   8
#define CAP    2048

// ---------------- scratch (allocation-free: __device__ globals) ------------
__device__ int   g_route[NTOK];
__device__ int   g_toklist[NEXP * CAP];
__device__ int   g_count[NEXP];
__device__ float g_h[(size_t)NEXP * CAP * DHID];   // 268 MB intermediate activations

// ---------------- router: logits + argmax (top_k = 1) ---------------------
__global__ __launch_bounds__(256) void moe_router(const float* __restrict__ x,
                                                  const float* __restrict__ Wg,
                                                  const float* __restrict__ bg) {
    __shared__ float sWgT[NEXP][DMODEL];
    int tid = threadIdx.x;
    for (int i = tid; i < DMODEL * NEXP; i += 256) {
        int d = i >> 3, e = i & 7;
        sWgT[e][d] = Wg[i];                // Wg is [d][e] row-major
    }
    __syncthreads();

    int wid = tid >> 5, lane = tid & 31;
    int token = blockIdx.x * 8 + wid;
    const float* xr = x + (size_t)token * DMODEL;

    float acc[NEXP];
#pragma unroll
    for (int e = 0; e < NEXP; e++) acc[e] = 0.f;

    for (int d = lane; d < DMODEL; d += 32) {
        float xv = xr[d];
#pragma unroll
        for (int e = 0; e < NEXP; e++) acc[e] += xv * sWgT[e][d];
    }
#pragma unroll
    for (int e = 0; e < NEXP; e++) {
#pragma unroll
        for (int off = 16; off > 0; off >>= 1)
            acc[e] += __shfl_xor_sync(0xffffffffu, acc[e], off);
    }
    if (lane == 0) {
        int best = 0;
        float bv = acc[0] + bg[0];
#pragma unroll
        for (int e = 1; e < NEXP; e++) {
            float v = acc[e] + bg[e];
            if (v > bv) { bv = v; best = e; }   // first-max tie-break
        }
        g_route[token] = best;
    }
}

// ---------------- ordered capacity scan ------------------------------------
__global__ __launch_bounds__(256) void moe_scan() {
    int tid = threadIdx.x;
    for (int i = tid; i < NEXP * CAP; i += 256) g_toklist[i] = -1;
    __syncthreads();

    int wid = tid >> 5, lane = tid & 31;   // wid == expert id
    int base = 0;
    for (int c = 0; c < NTOK / 32; c++) {
        int token = c * 32 + lane;
        int r = g_route[token];
        unsigned mask = __ballot_sync(0xffffffffu, r == wid);
        if (r == wid) {
            int pos = base + __popc(mask & ((1u << lane) - 1u));
            if (pos < CAP) g_toklist[wid * CAP + pos] = token;
        }
        base += __popc(mask);
    }
    if (lane == 0) g_count[wid] = base < CAP ? base : CAP;
}

// ---------------- 3xTF32 tensor-core GEMMs ---------------------------------
// Block tile 128x128, BK=32. 8 warps: 4 in M (32 rows each) x 2 in N (64 cols).
// Each warp: 2 m16-tiles x 8 n8-tiles of m16n8k8 tf32 mma, 3 mma per tile
// (hi*hi + lo*hi + hi*lo) for fp32-class accuracy.

#define BM 128
#define BN 128
#define BK 32
#define A_LD 36    // BK + 4 pad: frag banks (4*gid + tig) -> all distinct
#define B_LD 136   // BN + 8 pad: frag banks (8*tig + gid) -> all distinct

__device__ __forceinline__ uint32_t f2tf(float f) {
    uint32_t u;
    asm("cvt.rna.tf32.f32 %0, %1;" : "=r"(u) : "f"(f));
    return u;
}

__device__ __forceinline__ void mma_tf32(float* c, const uint32_t* a, const uint32_t* b) {
    asm volatile(
        "mma.sync.aligned.m16n8k8.row.col.f32.tf32.tf32.f32 "
        "{%0,%1,%2,%3}, {%4,%5,%6,%7}, {%8,%9}, {%0,%1,%2,%3};"
        : "+f"(c[0]), "+f"(c[1]), "+f"(c[2]), "+f"(c[3])
        : "r"(a[0]), "r"(a[1]), "r"(a[2]), "r"(a[3]), "r"(b[0]), "r"(b[1]));
}

// MODE 0: GEMM1  h = relu(x[tok] @ W1 + b1)   K=DMODEL, N=DHID
// MODE 1: GEMM2  out[tok] = h @ W2 + b2       K=DHID,   N=DMODEL
template <int MODE>
__global__ __launch_bounds__(256) void moe_ffn(const float* __restrict__ x,
                                               const float* __restrict__ W,
                                               const float* __restrict__ bias_g,
                                               float* __restrict__ outg) {
    const int K = (MODE == 0) ? DMODEL : DHID;
    const int N = (MODE == 0) ? DHID : DMODEL;

    int e = blockIdx.z;
    int count = g_count[e];
    int rowBase = blockIdx.y * BM;
    if (rowBase >= count) return;
    int colBase = blockIdx.x * BN;

    __shared__ float As[BM][A_LD];
    __shared__ float Bs[BK][B_LD];
    __shared__ int   sTok[BM];

    int tid = threadIdx.x;
    for (int i = tid; i < BM; i += 256) {
        int row = rowBase + i;
        sTok[i] = (row < count) ? g_toklist[e * CAP + row] : -1;
    }
    __syncthreads();

    const float* B    = W + (size_t)e * K * N + colBase;
    const float* bias = bias_g + (size_t)e * N + colBase;
    const float* hA   = g_h + ((size_t)e * CAP + rowBase) * DHID;  // MODE 1 A source

    int warpId = tid >> 5, lane = tid & 31;
    int warpM = warpId & 3;           // 0..3 -> M offset *32
    int warpN = warpId >> 2;          // 0..1 -> N offset *64
    int gid = lane >> 2, tig = lane & 3;

    float acc[2][8][4];
#pragma unroll
    for (int mi = 0; mi < 2; mi++)
#pragma unroll
        for (int ni = 0; ni < 8; ni++)
#pragma unroll
            for (int q = 0; q < 4; q++) acc[mi][ni][q] = 0.f;

    // per-thread copy indices
    int aRow = tid >> 1;               // 128 rows, 2 threads/row
    int aC4  = (tid & 1) * 4;          // two float4 slots per row handled over i-loop
    int bRow = tid >> 5;               // 8 k-rows per pass
    int bCol = (tid & 31) * 4;

    int tokA = (MODE == 0) ? sTok[aRow] : -1;
    bool aValid2 = (MODE == 1) && ((rowBase + aRow) < count);
    const float* aPtr = (MODE == 0)
        ? x + (size_t)(tokA >= 0 ? tokA : 0) * DMODEL
        : hA + (size_t)aRow * DHID;

    for (int k0 = 0; k0 < K; k0 += BK) {
        // ---- global -> SMEM ----
#pragma unroll
        for (int i = 0; i < 4; i++) {
            // A: 128 x 32 floats = 1024 float4; this thread covers row aRow,
            // k-chunks aC4 + i*8  (aC4 in {0,4}, +8 each pass -> covers 0..31)
            int kk = aC4 + i * 8;
            float4 av = make_float4(0.f, 0.f, 0.f, 0.f);
            if (MODE == 0) {
                if (tokA >= 0) av = *(const float4*)(aPtr + k0 + kk);
            } else {
                if (aValid2) av = *(const float4*)(aPtr + k0 + kk);
            }
            *(float4*)&As[aRow][kk] = av;

            // B: 32 x 128 floats = 1024 float4; k-row bRow + i*8
            int kr = bRow + i * 8;
            *(float4*)&Bs[kr][bCol] =
                *(const float4*)(B + (size_t)(k0 + kr) * N + bCol);
        }
        __syncthreads();

        // ---- compute: 4 k8 steps ----
#pragma unroll
        for (int s = 0; s < 4; s++) {
            int kk = s * 8;
            uint32_t aHi[2][4], aLo[2][4];
#pragma unroll
            for (int mi = 0; mi < 2; mi++) {
                int r0 = warpM * 32 + mi * 16 + gid;
                float f0 = As[r0][kk + tig];
                float f1 = As[r0 + 8][kk + tig];
                float f2 = As[r0][kk + tig + 4];
                float f3 = As[r0 + 8][kk + tig + 4];
                aHi[mi][0] = f2tf(f0); aLo[mi][0] = f2tf(f0 - __uint_as_float(aHi[mi][0]));
                aHi[mi][1] = f2tf(f1); aLo[mi][1] = f2tf(f1 - __uint_as_float(aHi[mi][1]));
                aHi[mi][2] = f2tf(f2); aLo[mi][2] = f2tf(f2 - __uint_as_float(aHi[mi][2]));
                aHi[mi][3] = f2tf(f3); aLo[mi][3] = f2tf(f3 - __uint_as_float(aHi[mi][3]));
            }
#pragma unroll
            for (int ni = 0; ni < 8; ni++) {
                int col = warpN * 64 + ni * 8 + gid;
                float b0 = Bs[kk + tig][col];
                float b1 = Bs[kk + tig + 4][col];
                uint32_t bHi[2], bLo[2];
                bHi[0] = f2tf(b0); bLo[0] = f2tf(b0 - __uint_as_float(bHi[0]));
                bHi[1] = f2tf(b1); bLo[1] = f2tf(b1 - __uint_as_float(bHi[1]));
#pragma unroll
                for (int mi = 0; mi < 2; mi++) {
                    mma_tf32(acc[mi][ni], aHi[mi], bHi);
                    mma_tf32(acc[mi][ni], aLo[mi], bHi);
                    mma_tf32(acc[mi][ni], aHi[mi], bLo);
                }
            }
        }
        __syncthreads();
    }

    // ---- epilogue ----
#pragma unroll
    for (int mi = 0; mi < 2; mi++) {
#pragma unroll
        for (int rr = 0; rr < 2; rr++) {           // rr=0 -> gid row, rr=1 -> gid+8
            int rloc = warpM * 32 + mi * 16 + gid + rr * 8;
            int tok = sTok[rloc];
            if (tok < 0) continue;
#pragma unroll
            for (int ni = 0; ni < 8; ni++) {
                int cloc = warpN * 64 + ni * 8 + tig * 2;
                float2 bv = *(const float2*)(bias + cloc);
                float v0 = acc[mi][ni][rr * 2 + 0] + bv.x;
                float v1 = acc[mi][ni][rr * 2 + 1] + bv.y;
                if (MODE == 0) {
                    v0 = v0 > 0.f ? v0 : 0.f;
                    v1 = v1 > 0.f ? v1 : 0.f;
                    float* op = g_h + ((size_t)e * CAP + rowBase + rloc) * DHID
                              + colBase + cloc;
                    *(float2*)op = make_float2(v0, v1);
                } else {
                    float* op = outg + (size_t)tok * DMODEL + colBase + cloc;
                    *(float2*)op = make_float2(v0, v1);
                }
            }
        }
    }
}

// ---------------- launch ----------------------------------------------------
extern "C" void kernel_launch(void* const* d_in, const int* in_sizes, int n_in,
                              void* d_out, int out_size) {
    const float* x  = (const float*)d_in[0];
    const float* Wg = (const float*)d_in[1];
    const float* bg = (const float*)d_in[2];
    const float* W1 = (const float*)d_in[3];
    const float* b1 = (const float*)d_in[4];
    const float* W2 = (const float*)d_in[5];
    const float* b2 = (const float*)d_in[6];
    float* out = (float*)d_out;

    cudaMemsetAsync(d_out, 0, (size_t)out_size * sizeof(float));

    moe_router<<<NTOK / 8, 256>>>(x, Wg, bg);
    moe_scan<<<1, 256>>>();
    moe_ffn<0><<<dim3(DHID / BN, CAP / BM, NEXP), 256>>>(x, W1, b1, nullptr);
    moe_ffn<1><<<dim3(DMODEL / BN, CAP / BM, NEXP), 256>>>(nullptr, W2, b2, out);
}

// round 3
// speedup vs baseline: 2.2981x; 1.6504x over previous
#include <cuda_runtime.h>
#include <cuda_bf16.h>
#include <cstdint>

// Problem constants (fixed by the reference)
#define NTOK   8192
#define DMODEL 1024
#define DHID   4096
#define NEXP   8
#define CAP    2048

// ---------------- scratch (allocation-free: __device__ globals) ------------
__device__ int   g_route[NTOK];
__device__ int   g_toklist[NEXP * CAP];
__device__ int   g_count[NEXP];
__device__ float g_h[(size_t)NEXP * CAP * DHID];   // 268 MB intermediate activations

// ---------------- router: logits + argmax (top_k = 1) ---------------------
__global__ __launch_bounds__(256) void moe_router(const float* __restrict__ x,
                                                  const float* __restrict__ Wg,
                                                  const float* __restrict__ bg) {
    __shared__ float sWgT[NEXP][DMODEL];
    int tid = threadIdx.x;
    for (int i = tid; i < DMODEL * NEXP; i += 256) {
        int d = i >> 3, e = i & 7;
        sWgT[e][d] = Wg[i];                // Wg is [d][e] row-major
    }
    __syncthreads();

    int wid = tid >> 5, lane = tid & 31;
    int token = blockIdx.x * 8 + wid;
    const float* xr = x + (size_t)token * DMODEL;

    float acc[NEXP];
#pragma unroll
    for (int e = 0; e < NEXP; e++) acc[e] = 0.f;

    for (int d = lane; d < DMODEL; d += 32) {
        float xv = xr[d];
#pragma unroll
        for (int e = 0; e < NEXP; e++) acc[e] += xv * sWgT[e][d];
    }
#pragma unroll
    for (int e = 0; e < NEXP; e++) {
#pragma unroll
        for (int off = 16; off > 0; off >>= 1)
            acc[e] += __shfl_xor_sync(0xffffffffu, acc[e], off);
    }
    if (lane == 0) {
        int best = 0;
        float bv = acc[0] + bg[0];
#pragma unroll
        for (int e = 1; e < NEXP; e++) {
            float v = acc[e] + bg[e];
            if (v > bv) { bv = v; best = e; }   // first-max tie-break
        }
        g_route[token] = best;
    }
}

// ---------------- ordered capacity scan ------------------------------------
__global__ __launch_bounds__(256) void moe_scan() {
    int tid = threadIdx.x;
    for (int i = tid; i < NEXP * CAP; i += 256) g_toklist[i] = -1;
    __syncthreads();

    int wid = tid >> 5, lane = tid & 31;   // wid == expert id
    int base = 0;
    for (int c = 0; c < NTOK / 32; c++) {
        int token = c * 32 + lane;
        int r = g_route[token];
        unsigned mask = __ballot_sync(0xffffffffu, r == wid);
        if (r == wid) {
            int pos = base + __popc(mask & ((1u << lane) - 1u));
            if (pos < CAP) g_toklist[wid * CAP + pos] = token;
        }
        base += __popc(mask);
    }
    if (lane == 0) g_count[wid] = base < CAP ? base : CAP;
}

// ---------------- 3xBF16 tensor-core GEMMs ---------------------------------
// Block tile 128x128, BK=32. 8 warps: 4 in M x 2 in N; each warp 32x64 via
// 2 m16 x 8 n8 tiles of mma.m16n8k16.bf16, 3 mma per tile (hi*hi+lo*hi+hi*lo).
// A/B pre-split into bf16 hi/lo in SMEM at copy time.

#define BM 128
#define BN 128
#define BK 32
#define A_STRIDE 40   // bf16 units per A row (80B): frag LDS hits 32 distinct banks

__device__ __forceinline__ uint32_t smem_u32(const void* p) {
    return (uint32_t)__cvta_generic_to_shared(p);
}

__device__ __forceinline__ void mma_bf16(float* c, const uint32_t* a, const uint32_t* b) {
    asm volatile(
        "mma.sync.aligned.m16n8k16.row.col.f32.bf16.bf16.f32 "
        "{%0,%1,%2,%3}, {%4,%5,%6,%7}, {%8,%9}, {%0,%1,%2,%3};"
        : "+f"(c[0]), "+f"(c[1]), "+f"(c[2]), "+f"(c[3])
        : "r"(a[0]), "r"(a[1]), "r"(a[2]), "r"(a[3]), "r"(b[0]), "r"(b[1]));
}

__device__ __forceinline__ void ldsm_x4_t(uint32_t& r0, uint32_t& r1,
                                          uint32_t& r2, uint32_t& r3, uint32_t addr) {
    asm volatile("ldmatrix.sync.aligned.m8n8.x4.trans.shared.b16 {%0,%1,%2,%3}, [%4];"
        : "=r"(r0), "=r"(r1), "=r"(r2), "=r"(r3) : "r"(addr));
}

// B tile byte offset with XOR swizzle (k row = 256B; spread bits[6:4] by k&7)
__device__ __forceinline__ uint32_t bswz(int k, int nbyte) {
    return (uint32_t)(k * 256 + (nbyte ^ ((k & 7) << 4)));
}

__device__ __forceinline__ uint32_t pack_hi2(float f0, float f1,
                                             float& r0, float& r1) {
    __nv_bfloat162 h = __floats2bfloat162_rn(f0, f1);   // .x = f0 (low half)
    r0 = f0 - __bfloat162float(h.x);
    r1 = f1 - __bfloat162float(h.y);
    return *(uint32_t*)&h;
}
__device__ __forceinline__ uint32_t pack_lo2(float r0, float r1) {
    __nv_bfloat162 l = __floats2bfloat162_rn(r0, r1);
    return *(uint32_t*)&l;
}

// MODE 0: GEMM1  h = relu(x[tok] @ W1 + b1)   K=DMODEL, N=DHID
// MODE 1: GEMM2  out[tok] = h @ W2 + b2       K=DHID,   N=DMODEL
template <int MODE>
__global__ __launch_bounds__(256) void moe_ffn(const float* __restrict__ x,
                                               const float* __restrict__ W,
                                               const float* __restrict__ bias_g,
                                               float* __restrict__ outg) {
    const int K = (MODE == 0) ? DMODEL : DHID;
    const int N = (MODE == 0) ? DHID : DMODEL;

    int e = blockIdx.z;
    int count = g_count[e];
    int rowBase = blockIdx.y * BM;
    if (rowBase >= count) return;
    int colBase = blockIdx.x * BN;

    __shared__ __align__(16) __nv_bfloat16 AsHi[BM * A_STRIDE];
    __shared__ __align__(16) __nv_bfloat16 AsLo[BM * A_STRIDE];
    __shared__ __align__(16) __nv_bfloat16 BsHi[BK * BN];   // swizzled layout
    __shared__ __align__(16) __nv_bfloat16 BsLo[BK * BN];
    __shared__ int sTok[BM];

    int tid = threadIdx.x;
    for (int i = tid; i < BM; i += 256) {
        int row = rowBase + i;
        sTok[i] = (row < count) ? g_toklist[e * CAP + row] : -1;
    }
    __syncthreads();

    const float* B    = W + (size_t)e * K * N + colBase;
    const float* bias = bias_g + (size_t)e * N + colBase;
    const float* hA   = g_h + ((size_t)e * CAP + rowBase) * DHID;

    int warpId = tid >> 5, lane = tid & 31;
    int warpM = warpId & 3;            // M offset *32
    int warpN = warpId >> 2;           // N offset *64
    int gid = lane >> 2, tig = lane & 3;

    uint32_t bHiBase = smem_u32(BsHi);
    uint32_t bLoBase = smem_u32(BsLo);
    // per-lane ldmatrix address component (independent of k16 step / n-panel)
    int lm_m  = lane >> 3;             // matrix index 0..3
    int lm_rr = lane & 7;
    int lm_kd = (lm_m & 1) * 8 + lm_rr;   // k offset within k16
    int lm_nd = (lm_m >> 1) * 8;          // n offset within n16 panel

    float acc[2][8][4];
#pragma unroll
    for (int mi = 0; mi < 2; mi++)
#pragma unroll
        for (int ni = 0; ni < 8; ni++)
#pragma unroll
            for (int q = 0; q < 4; q++) acc[mi][ni][q] = 0.f;

    // ---- copy-thread indices ----
    int aRow  = tid >> 1;              // A row handled by this thread
    int aHalf = (tid & 1) * 16;        // k offset 0 or 16
    int bK    = tid >> 5;              // B k row (0..7), +8 per i
    int bN    = lane * 4;              // B n offset (4 floats)

    int tokA = (MODE == 0) ? sTok[aRow] : -1;
    bool aValid = (MODE == 0) ? (tokA >= 0) : ((rowBase + aRow) < count);
    const float* aBase = (MODE == 0)
        ? x + (size_t)(tokA >= 0 ? tokA : 0) * DMODEL
        : hA + (size_t)aRow * DHID;

    float4 aReg[4], bReg[4];
    // prefetch k0 = 0
#pragma unroll
    for (int j = 0; j < 4; j++)
        aReg[j] = aValid ? *(const float4*)(aBase + aHalf + 4 * j)
                         : make_float4(0.f, 0.f, 0.f, 0.f);
#pragma unroll
    for (int i = 0; i < 4; i++)
        bReg[i] = *(const float4*)(B + (size_t)(bK + 8 * i) * N + bN);

    for (int k0 = 0; k0 < K; k0 += BK) {
        __syncthreads();   // SMEM free (prev iter's readers done)

        // ---- convert + store to SMEM ----
#pragma unroll
        for (int j = 0; j < 4; j++) {
            float r0, r1, r2, r3;
            uint32_t h01 = pack_hi2(aReg[j].x, aReg[j].y, r0, r1);
            uint32_t h23 = pack_hi2(aReg[j].z, aReg[j].w, r2, r3);
            uint32_t l01 = pack_lo2(r0, r1);
            uint32_t l23 = pack_lo2(r2, r3);
            int idx = aRow * A_STRIDE + aHalf + 4 * j;
            *(uint2*)&AsHi[idx] = make_uint2(h01, h23);
            *(uint2*)&AsLo[idx] = make_uint2(l01, l23);
        }
#pragma unroll
        for (int i = 0; i < 4; i++) {
            int kr = bK + 8 * i;
            float r0, r1, r2, r3;
            uint32_t h01 = pack_hi2(bReg[i].x, bReg[i].y, r0, r1);
            uint32_t h23 = pack_hi2(bReg[i].z, bReg[i].w, r2, r3);
            uint32_t l01 = pack_lo2(r0, r1);
            uint32_t l23 = pack_lo2(r2, r3);
            uint32_t off = bswz(kr, bN * 2);
            *(uint2*)((char*)BsHi + off) = make_uint2(h01, h23);
            *(uint2*)((char*)BsLo + off) = make_uint2(l01, l23);
        }
        __syncthreads();

        // ---- prefetch next slice (overlaps compute) ----
        if (k0 + BK < K) {
#pragma unroll
            for (int j = 0; j < 4; j++)
                aReg[j] = aValid ? *(const float4*)(aBase + k0 + BK + aHalf + 4 * j)
                                 : make_float4(0.f, 0.f, 0.f, 0.f);
#pragma unroll
            for (int i = 0; i < 4; i++)
                bReg[i] = *(const float4*)(B + (size_t)(k0 + BK + bK + 8 * i) * N + bN);
        }

        // ---- compute: 2 k16 steps ----
#pragma unroll
        for (int s = 0; s < 2; s++) {
            int kk = s * 16;
            uint32_t aHi[2][4], aLo[2][4];
#pragma unroll
            for (int mi = 0; mi < 2; mi++) {
                int r0 = (warpM * 32 + mi * 16 + gid) * A_STRIDE + kk + 2 * tig;
                int r1 = r0 + 8 * A_STRIDE;
                aHi[mi][0] = *(const uint32_t*)&AsHi[r0];
                aHi[mi][1] = *(const uint32_t*)&AsHi[r1];
                aHi[mi][2] = *(const uint32_t*)&AsHi[r0 + 8];
                aHi[mi][3] = *(const uint32_t*)&AsHi[r1 + 8];
                aLo[mi][0] = *(const uint32_t*)&AsLo[r0];
                aLo[mi][1] = *(const uint32_t*)&AsLo[r1];
                aLo[mi][2] = *(const uint32_t*)&AsLo[r0 + 8];
                aLo[mi][3] = *(const uint32_t*)&AsLo[r1 + 8];
            }
#pragma unroll
            for (int u = 0; u < 4; u++) {
                int n0 = warpN * 64 + u * 16;
                uint32_t off = bswz(kk + lm_kd, (n0 + lm_nd) * 2);
                uint32_t bh[4], bl[4];
                ldsm_x4_t(bh[0], bh[1], bh[2], bh[3], bHiBase + off);
                ldsm_x4_t(bl[0], bl[1], bl[2], bl[3], bLoBase + off);
#pragma unroll
                for (int v = 0; v < 2; v++) {       // two n8 tiles in this panel
                    int ni = u * 2 + v;
                    uint32_t bhp[2] = { bh[v * 2 + 0], bh[v * 2 + 1] };
                    uint32_t blp[2] = { bl[v * 2 + 0], bl[v * 2 + 1] };
#pragma unroll
                    for (int mi = 0; mi < 2; mi++) {
                        mma_bf16(acc[mi][ni], aHi[mi], bhp);
                        mma_bf16(acc[mi][ni], aLo[mi], bhp);
                        mma_bf16(acc[mi][ni], aHi[mi], blp);
                    }
                }
            }
        }
    }

    // ---- epilogue ----
#pragma unroll
    for (int mi = 0; mi < 2; mi++) {
#pragma unroll
        for (int rr = 0; rr < 2; rr++) {
            int rloc = warpM * 32 + mi * 16 + gid + rr * 8;
            int tok = sTok[rloc];
            if (tok < 0) continue;
#pragma unroll
            for (int ni = 0; ni < 8; ni++) {
                int cloc = warpN * 64 + ni * 8 + tig * 2;
                float2 bv = *(const float2*)(bias + cloc);
                float v0 = acc[mi][ni][rr * 2 + 0] + bv.x;
                float v1 = acc[mi][ni][rr * 2 + 1] + bv.y;
                if (MODE == 0) {
                    v0 = v0 > 0.f ? v0 : 0.f;
                    v1 = v1 > 0.f ? v1 : 0.f;
                    float* op = g_h + ((size_t)e * CAP + rowBase + rloc) * DHID
                              + colBase + cloc;
                    *(float2*)op = make_float2(v0, v1);
                } else {
                    float* op = outg + (size_t)tok * DMODEL + colBase + cloc;
                    *(float2*)op = make_float2(v0, v1);
                }
            }
        }
    }
}

// ---------------- launch ----------------------------------------------------
extern "C" void kernel_launch(void* const* d_in, const int* in_sizes, int n_in,
                              void* d_out, int out_size) {
    const float* x  = (const float*)d_in[0];
    const float* Wg = (const float*)d_in[1];
    const float* bg = (const float*)d_in[2];
    const float* W1 = (const float*)d_in[3];
    const float* b1 = (const float*)d_in[4];
    const float* W2 = (const float*)d_in[5];
    const float* b2 = (const float*)d_in[6];
    float* out = (float*)d_out;

    cudaMemsetAsync(d_out, 0, (size_t)out_size * sizeof(float));

    moe_router<<<NTOK / 8, 256>>>(x, Wg, bg);
    moe_scan<<<1, 256>>>();
    moe_ffn<0><<<dim3(DHID / BN, CAP / BM, NEXP), 256>>>(x, W1, b1, nullptr);
    moe_ffn<1><<<dim3(DMODEL / BN, CAP / BM, NEXP), 256>>>(nullptr, W2, b2, out);
}